// round 7
// baseline (speedup 1.0000x reference)
#include <cuda_runtime.h>
#include <cuda_bf16.h>

// Problem constants: input shape (N=4, C=3, 128,128,128), fp32.
#define S_SPATIAL (128 * 128 * 128)          // 2,097,152 contiguous elems per (n,c) segment
#define N_BATCH   4
#define C_CHAN    3
#define N_SEG     (N_BATCH * C_CHAN)          // 12 contiguous segments
#define M_PER_CH  ((long long)N_BATCH * S_SPATIAL)   // 8,388,608 elems per channel

#define BLOCKS_PER_SEG 64
#define THREADS        256
#define ELEMS_PER_BLK  (S_SPATIAL / BLOCKS_PER_SEG)  // 32768
#define VEC4_PER_BLK   (ELEMS_PER_BLK / 4)           // 8192

// Scratch accumulators (no device allocation allowed; __device__ globals are the
// sanctioned workaround). Re-zeroed every launch by the init kernel so graph
// replays are deterministic.
__device__ double             g_sum[C_CHAN];
__device__ unsigned long long g_cnt[C_CHAN];

__global__ void bce_init_kernel() {
    int i = threadIdx.x;
    if (i < C_CHAN) {
        g_sum[i] = 0.0;
        g_cnt[i] = 0ull;
    }
}

__global__ __launch_bounds__(THREADS) void bce_reduce_kernel(
    const float* __restrict__ p_in,
    const float* __restrict__ t_in)
{
    const int seg   = blockIdx.x >> 6;        // blockIdx.x / 64
    const int chunk = blockIdx.x & 63;
    const int c     = seg % C_CHAN;           // channel is uniform per block

    const size_t base = (size_t)seg * S_SPATIAL + (size_t)chunk * ELEMS_PER_BLK;
    const float4* __restrict__ p4 = (const float4*)(p_in + base);
    const float4* __restrict__ t4 = (const float4*)(t_in + base);

    float sum = 0.0f;
    int   cnt = 0;

    #pragma unroll 4
    for (int i = threadIdx.x; i < VEC4_PER_BLK; i += THREADS) {
        float4 pv = p4[i];
        float4 tv = t4[i];

        {
            bool one = (tv.x != 0.0f);
            float x = one ? pv.x : (1.0f - pv.x);
            sum += fmaxf(__logf(x), -100.0f);
            cnt += one;
        }
        {
            bool one = (tv.y != 0.0f);
            float x = one ? pv.y : (1.0f - pv.y);
            sum += fmaxf(__logf(x), -100.0f);
            cnt += one;
        }
        {
            bool one = (tv.z != 0.0f);
            float x = one ? pv.z : (1.0f - pv.z);
            sum += fmaxf(__logf(x), -100.0f);
            cnt += one;
        }
        {
            bool one = (tv.w != 0.0f);
            float x = one ? pv.w : (1.0f - pv.w);
            sum += fmaxf(__logf(x), -100.0f);
            cnt += one;
        }
    }

    // Warp reduction
    #pragma unroll
    for (int off = 16; off > 0; off >>= 1) {
        sum += __shfl_xor_sync(0xFFFFFFFFu, sum, off);
        cnt += __shfl_xor_sync(0xFFFFFFFFu, cnt, off);
    }

    // Block reduction across 8 warps
    __shared__ float s_sum[THREADS / 32];
    __shared__ int   s_cnt[THREADS / 32];
    const int wid = threadIdx.x >> 5;
    const int lid = threadIdx.x & 31;
    if (lid == 0) {
        s_sum[wid] = sum;
        s_cnt[wid] = cnt;
    }
    __syncthreads();

    if (threadIdx.x == 0) {
        float bsum = 0.0f;
        int   bcnt = 0;
        #pragma unroll
        for (int w = 0; w < THREADS / 32; w++) {
            bsum += s_sum[w];
            bcnt += s_cnt[w];
        }
        atomicAdd(&g_sum[c], (double)bsum);
        atomicAdd(&g_cnt[c], (unsigned long long)bcnt);
    }
}

__global__ void bce_final_kernel(float* __restrict__ out) {
    double total = 0.0;
    #pragma unroll
    for (int c = 0; c < C_CHAN; c++) {
        double s    = g_sum[c];
        double ones = (double)g_cnt[c];
        double bce  = -s / (double)M_PER_CH;                       // mean over channel row, negated
        double w    = (ones > 0.0) ? ((double)M_PER_CH / ones)     // total / ones
                                   : 1000.0;                       // EMPTY_WEIGHT
        total += w * bce;
    }
    out[0] = (float)(total / (double)C_CHAN);
}

extern "C" void kernel_launch(void* const* d_in, const int* in_sizes, int n_in,
                              void* d_out, int out_size) {
    const float* input  = (const float*)d_in[0];
    const float* target = (const float*)d_in[1];
    float* out = (float*)d_out;

    bce_init_kernel<<<1, 32>>>();
    bce_reduce_kernel<<<N_SEG * BLOCKS_PER_SEG, THREADS>>>(input, target);
    bce_final_kernel<<<1, 1>>>(out);
}

// round 8
// speedup vs baseline: 1.0366x; 1.0366x over previous
#include <cuda_runtime.h>
#include <cuda_bf16.h>

// Problem constants: input shape (N=4, C=3, 128,128,128), fp32.
#define S_SPATIAL (128 * 128 * 128)          // 2,097,152 contiguous elems per (n,c) segment
#define N_BATCH   4
#define C_CHAN    3
#define N_SEG     (N_BATCH * C_CHAN)          // 12 contiguous segments
#define M_PER_CH  ((long long)N_BATCH * S_SPATIAL)   // 8,388,608 elems per channel

#define BLOCKS_PER_SEG 64
#define THREADS        256
#define ELEMS_PER_BLK  (S_SPATIAL / BLOCKS_PER_SEG)  // 32768
#define VEC4_PER_BLK   (ELEMS_PER_BLK / 4)           // 8192

// Scratch accumulators (no device allocation allowed; __device__ globals are the
// sanctioned workaround). Re-zeroed every launch by the init kernel so graph
// replays are deterministic.
__device__ double             g_sum[C_CHAN];
__device__ unsigned long long g_cnt[C_CHAN];

__global__ void bce_init_kernel() {
    int i = threadIdx.x;
    if (i < C_CHAN) {
        g_sum[i] = 0.0;
        g_cnt[i] = 0ull;
    }
}

__global__ __launch_bounds__(THREADS) void bce_reduce_kernel(
    const float* __restrict__ p_in,
    const float* __restrict__ t_in)
{
    const int seg   = blockIdx.x >> 6;        // blockIdx.x / 64
    const int chunk = blockIdx.x & 63;
    const int c     = seg % C_CHAN;           // channel is uniform per block

    const size_t base = (size_t)seg * S_SPATIAL + (size_t)chunk * ELEMS_PER_BLK;
    const float4* __restrict__ p4 = (const float4*)(p_in + base);
    const float4* __restrict__ t4 = (const float4*)(t_in + base);

    float sum = 0.0f;
    int   cnt = 0;

    #pragma unroll 4
    for (int i = threadIdx.x; i < VEC4_PER_BLK; i += THREADS) {
        float4 pv = p4[i];
        float4 tv = t4[i];

        {
            bool one = (tv.x != 0.0f);
            float x = one ? pv.x : (1.0f - pv.x);
            sum += fmaxf(__logf(x), -100.0f);
            cnt += one;
        }
        {
            bool one = (tv.y != 0.0f);
            float x = one ? pv.y : (1.0f - pv.y);
            sum += fmaxf(__logf(x), -100.0f);
            cnt += one;
        }
        {
            bool one = (tv.z != 0.0f);
            float x = one ? pv.z : (1.0f - pv.z);
            sum += fmaxf(__logf(x), -100.0f);
            cnt += one;
        }
        {
            bool one = (tv.w != 0.0f);
            float x = one ? pv.w : (1.0f - pv.w);
            sum += fmaxf(__logf(x), -100.0f);
            cnt += one;
        }
    }

    // Warp reduction
    #pragma unroll
    for (int off = 16; off > 0; off >>= 1) {
        sum += __shfl_xor_sync(0xFFFFFFFFu, sum, off);
        cnt += __shfl_xor_sync(0xFFFFFFFFu, cnt, off);
    }

    // Block reduction across 8 warps
    __shared__ float s_sum[THREADS / 32];
    __shared__ int   s_cnt[THREADS / 32];
    const int wid = threadIdx.x >> 5;
    const int lid = threadIdx.x & 31;
    if (lid == 0) {
        s_sum[wid] = sum;
        s_cnt[wid] = cnt;
    }
    __syncthreads();

    if (threadIdx.x == 0) {
        float bsum = 0.0f;
        int   bcnt = 0;
        #pragma unroll
        for (int w = 0; w < THREADS / 32; w++) {
            bsum += s_sum[w];
            bcnt += s_cnt[w];
        }
        atomicAdd(&g_sum[c], (double)bsum);
        atomicAdd(&g_cnt[c], (unsigned long long)bcnt);
    }
}

__global__ void bce_final_kernel(float* __restrict__ out) {
    double total = 0.0;
    #pragma unroll
    for (int c = 0; c < C_CHAN; c++) {
        double s    = g_sum[c];
        double ones = (double)g_cnt[c];
        double bce  = -s / (double)M_PER_CH;                       // mean over channel row, negated
        double w    = (ones > 0.0) ? ((double)M_PER_CH / ones)     // total / ones
                                   : 1000.0;                       // EMPTY_WEIGHT
        total += w * bce;
    }
    out[0] = (float)(total / (double)C_CHAN);
}

extern "C" void kernel_launch(void* const* d_in, const int* in_sizes, int n_in,
                              void* d_out, int out_size) {
    const float* input  = (const float*)d_in[0];
    const float* target = (const float*)d_in[1];
    float* out = (float*)d_out;

    bce_init_kernel<<<1, 32>>>();
    bce_reduce_kernel<<<N_SEG * BLOCKS_PER_SEG, THREADS>>>(input, target);
    bce_final_kernel<<<1, 1>>>(out);
}